// round 16
// baseline (speedup 1.0000x reference)
#include <cuda_runtime.h>
#include <cstdint>
#include <cstddef>

// Problem constants
#define BB 256
#define SS 16
#define HH 8
#define HSZ 128
#define DD 1024
#define MM 1024
#define ROWS_L (BB*SS)               // 4096
#define N_ELEM ((size_t)ROWS_L*MM)   // 4,194,304

// uber grid layout
#define N_GEMM_BLK 832               // jobs 0-3: 16 CTAs each; jobs 4-6: 256 each
#define N_ATTN_BLK (BB*HH)           // 2048
#define ATTN_BASE  N_GEMM_BLK        // 832
#define MP2_BASE   (N_GEMM_BLK + N_ATTN_BLK)   // 2880
#define N_UBER_BLK (MP2_BASE + 256)  // 3136
#define DENSE_TARGET 16u
#define PRE_TARGET   (48u + 768u + 2048u)      // proj(1-3) + gates + attn

// ---------------- scratch ----------------
__device__ float g_dense[BB*MM];
__device__ float g_xf[BB*MM];
__device__ float g_xi[BB*MM];
__device__ float g_xo[BB*MM];
__device__ float g_mp[ROWS_L*MM];
__device__ float g_gf[ROWS_L*MM];
__device__ float g_gi[ROWS_L*MM];
__device__ float g_go[ROWS_L*MM];
__device__ float g_wT[8][MM*MM];     // transposed weights [N][K]
__device__ unsigned g_cnt_dense;
__device__ unsigned g_cnt_pre;

struct UberArgs {
    // 7 independent GEMMs (0: dense, 1-3: x-projections, 4-6: gates)
    const float* A[7];
    const float* BT[7];
    const float* bias[7];
    float*       C[7];
    // attention
    const float* m_state;
    float*       mp;       // g_mp
    // fused mp2 + final gating
    const float* BTg;      // W_g^T
    const float* bg;
    float*       out;      // d_out [2, ROWS_L, MM]
};
struct TPtrs { const float* src[8]; float* dst[8]; };

__device__ __forceinline__ uint32_t smem_u32(const void* p) {
    return (uint32_t)__cvta_generic_to_shared(p);
}
__device__ __forceinline__ void cp16(uint32_t dst, const void* src) {
    asm volatile("cp.async.cg.shared.global [%0], [%1], 16;" :: "r"(dst), "l"(src));
}
__device__ __forceinline__ void cp_commit() {
    asm volatile("cp.async.commit_group;" ::: "memory");
}
template <int N>
__device__ __forceinline__ void cp_wait() {
    asm volatile("cp.async.wait_group %0;" :: "n"(N) : "memory");
}
__device__ __forceinline__ void ldsm4(uint32_t& r0, uint32_t& r1,
                                      uint32_t& r2, uint32_t& r3, uint32_t addr) {
    asm volatile("ldmatrix.sync.aligned.m8n8.x4.shared.b16 {%0,%1,%2,%3}, [%4];"
                 : "=r"(r0), "=r"(r1), "=r"(r2), "=r"(r3) : "r"(addr));
}
__device__ __forceinline__ void mma_tf32(
    float& d0, float& d1, float& d2, float& d3,
    uint32_t a0, uint32_t a1, uint32_t a2, uint32_t a3,
    uint32_t b0, uint32_t b1)
{
    asm volatile(
        "mma.sync.aligned.m16n8k8.row.col.f32.tf32.tf32.f32 "
        "{%0,%1,%2,%3}, {%4,%5,%6,%7}, {%8,%9}, {%0,%1,%2,%3};\n"
        : "+f"(d0), "+f"(d1), "+f"(d2), "+f"(d3)
        : "r"(a0), "r"(a1), "r"(a2), "r"(a3), "r"(b0), "r"(b1));
}
__device__ __forceinline__ float sigm(float x) { return 1.f / (1.f + expf(-x)); }

// flag sync: producers publish after threadfence; consumer spins (tid 0) then
// syncthreads. Safe: CTAs dispatch in bid order; dense CTAs (bids 0-15) are in
// wave 1; spinners can never starve lower-bid producers.
__device__ __forceinline__ void signal_cnt(unsigned* cnt) {
    __threadfence();
    __syncthreads();
    if (threadIdx.x == 0) atomicAdd(cnt, 1u);
}
__device__ __forceinline__ void wait_cnt(unsigned* cnt, unsigned target) {
    if (threadIdx.x == 0) {
        while (atomicAdd(cnt, 0u) < target) {}
    }
    __syncthreads();
}

// ---------------- weight transpose (8 matrices 1024x1024) + flag reset ----
__global__ void __launch_bounds__(256) transpose_k(TPtrs tp)
{
    __shared__ float tile[32][33];
    if (blockIdx.x == 0 && blockIdx.y == 0 && blockIdx.z == 0 &&
        threadIdx.x == 0 && threadIdx.y == 0) {
        g_cnt_dense = 0u;
        g_cnt_pre = 0u;
    }
    const float* __restrict__ in = tp.src[blockIdx.z];
    float* __restrict__ out      = tp.dst[blockIdx.z];
    const int tx = threadIdx.x, ty = threadIdx.y;   // block (32, 8)
    const int x = blockIdx.x * 32 + tx;
    const int y0 = blockIdx.y * 32 + ty;
#pragma unroll
    for (int j = 0; j < 32; j += 8)
        tile[ty + j][tx] = in[(size_t)(y0 + j) * MM + x];
    __syncthreads();
    const int x2 = blockIdx.y * 32 + tx;
    const int y2 = blockIdx.x * 32 + ty;
#pragma unroll
    for (int j = 0; j < 32; j += 8)
        out[(size_t)(y2 + j) * MM + x2] = tile[tx][ty + j];
}

// ---------------- TF32 GEMM mainloop: cp.async 3-stage, SW128, ldmatrix ---
#define BKT 32
#define TILE_B 16384
#define STAGE_B (2 * TILE_B)
#define NSTAGE 3
#define GEMM_SMEM (NSTAGE * STAGE_B)  // 96 KB

__device__ __forceinline__ void stage_tile(
    const float* __restrict__ Ablk, const float* __restrict__ Bblk,
    int K, int k0, uint32_t bufA, uint32_t bufB, int tid)
{
#pragma unroll
    for (int i = 0; i < 4; i++) {
        const int c = tid + 256 * i;
        const int row = c >> 3, q = c & 7;
        const uint32_t off = row * 128 + ((q * 16) ^ ((row & 7) << 4));
        cp16(bufA + off, Ablk + (size_t)row * K + k0 + q * 4);
        cp16(bufB + off, Bblk + (size_t)row * K + k0 + q * 4);
    }
}

__device__ __forceinline__ void gemm_mainloop(
    const float* __restrict__ A, const float* __restrict__ BT,
    int K, int bx, int by, char* dynsm, float acc[2][8][4])
{
    const uint32_t sm0 = smem_u32(dynsm);
    const int tid = threadIdx.x, warp = tid >> 5, lane = tid & 31;
    const int warpM = (warp >> 1) * 32;
    const int warpN = (warp & 1) * 64;

    const float* __restrict__ Ablk = A + (size_t)by * 128 * K;
    const float* __restrict__ Bblk = BT + (size_t)bx * 128 * K;

    uint32_t aBase[2], aKey[2];
    {
        const uint32_t r = (lane & 7) + ((lane >> 3) & 1) * 8;
        const uint32_t cb = (lane >> 4) * 16;
#pragma unroll
        for (int mf = 0; mf < 2; mf++) {
            const uint32_t row = warpM + mf * 16 + r;
            aBase[mf] = row * 128;
            aKey[mf]  = ((row & 7) << 4) ^ cb;
        }
    }
    uint32_t bBase[4], bKey[4];
    {
        const uint32_t r = (lane & 7) + ((lane >> 4) & 1) * 8;
        const uint32_t cb = ((lane >> 3) & 1) * 16;
#pragma unroll
        for (int p = 0; p < 4; p++) {
            const uint32_t row = warpN + p * 16 + r;
            bBase[p] = row * 128;
            bKey[p]  = ((row & 7) << 4) ^ cb;
        }
    }

#pragma unroll
    for (int i = 0; i < 2; i++)
#pragma unroll
        for (int j = 0; j < 8; j++)
#pragma unroll
            for (int q = 0; q < 4; q++) acc[i][j][q] = 0.f;

    const int nt = K / BKT;

    stage_tile(Ablk, Bblk, K, 0, sm0, sm0 + TILE_B, tid);
    cp_commit();
    stage_tile(Ablk, Bblk, K, BKT, sm0 + STAGE_B, sm0 + STAGE_B + TILE_B, tid);
    cp_commit();

    for (int t = 0; t < nt; t++) {
        cp_wait<1>();
        __syncthreads();   // single barrier: also orders compute(t-1) before
                           // staging into slot (t+2)%3 == (t-1)%3

        if (t + 2 < nt) {
            const uint32_t sb = sm0 + ((t + 2) % NSTAGE) * STAGE_B;
            stage_tile(Ablk, Bblk, K, (t + 2) * BKT, sb, sb + TILE_B, tid);
        }
        cp_commit();

        const uint32_t abuf = sm0 + (t % NSTAGE) * STAGE_B;
        const uint32_t bbuf = abuf + TILE_B;

#pragma unroll
        for (int ks = 0; ks < BKT; ks += 8) {
            const uint32_t boff = ks * 4;
            uint32_t afr[2][4], bfr[8][2];
#pragma unroll
            for (int mf = 0; mf < 2; mf++)
                ldsm4(afr[mf][0], afr[mf][1], afr[mf][2], afr[mf][3],
                      abuf + aBase[mf] + (boff ^ aKey[mf]));
#pragma unroll
            for (int p = 0; p < 4; p++)
                ldsm4(bfr[2*p][0], bfr[2*p][1], bfr[2*p+1][0], bfr[2*p+1][1],
                      bbuf + bBase[p] + (boff ^ bKey[p]));
#pragma unroll
            for (int mf = 0; mf < 2; mf++)
#pragma unroll
                for (int nf = 0; nf < 8; nf++)
                    mma_tf32(acc[mf][nf][0], acc[mf][nf][1],
                             acc[mf][nf][2], acc[mf][nf][3],
                             afr[mf][0], afr[mf][1], afr[mf][2], afr[mf][3],
                             bfr[nf][0], bfr[nf][1]);
        }
    }
}

// ---------------- uber kernel: all GEMMs + attention + fused final --------
__global__ void __launch_bounds__(256, 2) uber_kernel(UberArgs ua)
{
    extern __shared__ char dynsm[];
    const int id = blockIdx.x;
    const int tid = threadIdx.x;

    if (id < N_GEMM_BLK) {
        // ---------------- 7 independent GEMMs ----------------
        int job, bx, by;
        if (id < 64) {
            job = id >> 4;
            const int rem = id & 15;
            bx = rem & 7; by = rem >> 3;
        } else {
            const int t2 = id - 64;
            job = 4 + (t2 >> 8);
            const int rem = t2 & 255;
            bx = rem & 7; by = rem >> 3;
        }
        float acc[2][8][4];
        gemm_mainloop(ua.A[job], ua.BT[job], MM, bx, by, dynsm, acc);

        const float* __restrict__ bias = ua.bias[job];
        float* __restrict__ C          = ua.C[job];
        const int warp = tid >> 5, lane = tid & 31;
        const int tig = lane & 3, gid = lane >> 2;
        const int row0 = by * 128 + (warp >> 1) * 32;
        const int col0 = bx * 128 + (warp & 1) * 64;
#pragma unroll
        for (int mf = 0; mf < 2; mf++) {
#pragma unroll
            for (int nf = 0; nf < 8; nf++) {
                const int c = col0 + nf * 8 + 2 * tig;
                float bv0 = 0.f, bv1 = 0.f;
                if (bias) { bv0 = bias[c]; bv1 = bias[c + 1]; }
#pragma unroll
                for (int half = 0; half < 2; half++) {
                    const int r = row0 + mf * 16 + gid + half * 8;
                    float2 out = { acc[mf][nf][half * 2 + 0] + bv0,
                                   acc[mf][nf][half * 2 + 1] + bv1 };
                    *(float2*)(C + (size_t)r * MM + c) = out;
                }
            }
        }
        signal_cnt(job == 0 ? &g_cnt_dense : &g_cnt_pre);

    } else if (id < MP2_BASE) {
        // ---------------- attention (needs g_dense only) ----------------
        wait_cnt(&g_cnt_dense, DENSE_TARGET);

        const int bh = id - ATTN_BASE;
        const int b = bh >> 3;
        const int h = bh & 7;
        float (*kv)[128] = (float(*)[128])dynsm;
        float (*sc)[18]  = (float(*)[18])(dynsm + 17 * 128 * 4);

        const float* mbase = ua.m_state + (size_t)b * SS * MM + h * HSZ;
        for (int idx = tid; idx < 16 * 128; idx += 256) {
            int j = idx >> 7, d = idx & 127;
            kv[j][d] = mbase[(size_t)j * MM + d];
        }
        if (tid < 128) kv[16][tid] = g_dense[(size_t)b * MM + h * HSZ + tid];
        __syncthreads();

        const int warp = tid >> 5, lane = tid & 31;
        for (int s = warp; s < 16 * 17; s += 8) {
            const int i = s / 17, j = s % 17;
            float sum = 0.f;
#pragma unroll
            for (int t = 0; t < 4; t++)
                sum += kv[i][lane + t * 32] * kv[j][lane + t * 32];
#pragma unroll
            for (int off = 16; off; off >>= 1)
                sum += __shfl_xor_sync(0xffffffff, sum, off);
            if (lane == 0) sc[i][j] = sum * 0.08838834764831845f;
        }
        __syncthreads();

        if (tid < 16) {
            float mx = -1e30f;
#pragma unroll
            for (int j = 0; j < 17; j++) mx = fmaxf(mx, sc[tid][j]);
            float sum = 0.f;
#pragma unroll
            for (int j = 0; j < 17; j++) {
                float e = expf(sc[tid][j] - mx);
                sc[tid][j] = e;
                sum += e;
            }
            const float inv = 1.f / sum;
#pragma unroll
            for (int j = 0; j < 17; j++) sc[tid][j] *= inv;
        }
        __syncthreads();

        for (int idx = tid; idx < 16 * 128; idx += 256) {
            const int i = idx >> 7, d = idx & 127;
            float a = 0.f;
#pragma unroll
            for (int j = 0; j < 17; j++) a += sc[i][j] * kv[j][d];
            ua.mp[((size_t)b * SS + i) * MM + h * HSZ + d] = kv[i][d] + a;
        }
        signal_cnt(&g_cnt_pre);

    } else {
        // ------- fused mp2 GEMM + final gating (needs proj+gates+attn) ----
        wait_cnt(&g_cnt_pre, PRE_TARGET);

        const int t2 = id - MP2_BASE;
        const int bx = t2 & 7, by = t2 >> 3;
        float acc[2][8][4];
        gemm_mainloop(ua.mp, ua.BTg, MM, bx, by, dynsm, acc);

        // stage acc to smem (stride 132 words, float4-aligned rows)
        __syncthreads();   // all warps done with mainloop smem
        float* sC = (float*)dynsm;
        {
            const int warp = tid >> 5, lane = tid & 31;
            const int tig = lane & 3, gid = lane >> 2;
            const int rw0 = (warp >> 1) * 32;
            const int cw0 = (warp & 1) * 64;
#pragma unroll
            for (int mf = 0; mf < 2; mf++)
#pragma unroll
                for (int nf = 0; nf < 8; nf++)
#pragma unroll
                    for (int half = 0; half < 2; half++) {
                        const int rl = rw0 + mf * 16 + gid + half * 8;
                        const int cl = cw0 + nf * 8 + 2 * tig;
                        float2 v = { acc[mf][nf][half * 2 + 0],
                                     acc[mf][nf][half * 2 + 1] };
                        *(float2*)(sC + rl * 132 + cl) = v;
                    }
        }
        __syncthreads();

        // coalesced fused epilogue: warp covers one 128-float row span
        const int row0 = by * 128, col0 = bx * 128;
#pragma unroll
        for (int it = 0; it < 16; it++) {
            const int g = tid + 256 * it;
            const int rl = g >> 5;            // 0..127
            const int cl = (g & 31) * 4;      // 0..124
            const int r = row0 + rl;
            const int c = col0 + cl;
            const size_t idx  = (size_t)r * MM + c;
            const size_t xidx = (size_t)(r >> 4) * MM + c;

            const float4 av  = *(const float4*)(sC + rl * 132 + cl);
            const float4 bgv = *(const float4*)(ua.bg + c);
            const float4 mpv = *(const float4*)(ua.mp + idx);
            const float4 mv  = *(const float4*)(ua.m_state + idx);
            const float4 f4  = *(const float4*)(g_gf + idx);
            const float4 i4  = *(const float4*)(g_gi + idx);
            const float4 o4  = *(const float4*)(g_go + idx);
            const float4 fx  = *(const float4*)(g_xf + xidx);
            const float4 ix  = *(const float4*)(g_xi + xidx);
            const float4 ox  = *(const float4*)(g_xo + xidx);

            const float p0 = av.x + bgv.x + mpv.x;
            const float p1 = av.y + bgv.y + mpv.y;
            const float p2 = av.z + bgv.z + mpv.z;
            const float p3 = av.w + bgv.w + mpv.w;

            float4 nm, nh;
            nm.x = sigm(mv.x * sigm(f4.x + fx.x) + 1.f) + p0 * sigm(sigm(i4.x + ix.x));
            nm.y = sigm(mv.y * sigm(f4.y + fx.y) + 1.f) + p1 * sigm(sigm(i4.y + ix.y));
            nm.z = sigm(mv.z * sigm(f4.z + fx.z) + 1.f) + p2 * sigm(sigm(i4.z + ix.z));
            nm.w = sigm(mv.w * sigm(f4.w + fx.w) + 1.f) + p3 * sigm(sigm(i4.w + ix.w));

            nh.x = tanhf(mv.x) * sigm(sigm(o4.x + ox.x));
            nh.y = tanhf(mv.y) * sigm(sigm(o4.y + ox.y));
            nh.z = tanhf(mv.z) * sigm(sigm(o4.z + ox.z));
            nh.w = tanhf(mv.w) * sigm(sigm(o4.w + ox.w));

            *(float4*)(ua.out + idx) = nm;
            *(float4*)(ua.out + N_ELEM + idx) = nh;
        }
    }
}

// ---------------- launch ----------------
extern "C" void kernel_launch(void* const* d_in, const int* in_sizes, int n_in,
                              void* d_out, int out_size)
{
    const float* inputs  = (const float*)d_in[0];
    const float* h_state = (const float*)d_in[1];
    const float* m_state = (const float*)d_in[2];
    const float* W_emb   = (const float*)d_in[3];
    const float* b_emb   = (const float*)d_in[4];
    const float* W_g     = (const float*)d_in[5];
    const float* b_g     = (const float*)d_in[6];
    const float* W_wf    = (const float*)d_in[7];
    const float* W_wi    = (const float*)d_in[8];
    const float* W_wo    = (const float*)d_in[9];
    const float* W_uf    = (const float*)d_in[10];
    const float* b_uf    = (const float*)d_in[11];
    const float* W_ui    = (const float*)d_in[12];
    const float* b_ui    = (const float*)d_in[13];
    const float* W_uo    = (const float*)d_in[14];
    const float* b_uo    = (const float*)d_in[15];

    float *p_dense, *p_xf, *p_xi, *p_xo, *p_mp, *p_gf, *p_gi, *p_go, *p_wT;
    cudaGetSymbolAddress((void**)&p_dense, g_dense);
    cudaGetSymbolAddress((void**)&p_xf, g_xf);
    cudaGetSymbolAddress((void**)&p_xi, g_xi);
    cudaGetSymbolAddress((void**)&p_xo, g_xo);
    cudaGetSymbolAddress((void**)&p_mp, g_mp);
    cudaGetSymbolAddress((void**)&p_gf, g_gf);
    cudaGetSymbolAddress((void**)&p_gi, g_gi);
    cudaGetSymbolAddress((void**)&p_go, g_go);
    cudaGetSymbolAddress((void**)&p_wT, g_wT);

    float* wt[8];
    for (int i = 0; i < 8; i++) wt[i] = p_wT + (size_t)i * MM * MM;

    cudaFuncSetAttribute(uber_kernel, cudaFuncAttributeMaxDynamicSharedMemorySize,
                         GEMM_SMEM);

    // 0) transpose all 8 weight matrices + reset sync counters
    {
        TPtrs tp;
        tp.src[0] = W_emb; tp.src[1] = W_wf; tp.src[2] = W_wi; tp.src[3] = W_wo;
        tp.src[4] = W_uf;  tp.src[5] = W_ui; tp.src[6] = W_uo; tp.src[7] = W_g;
        for (int i = 0; i < 8; i++) tp.dst[i] = wt[i];
        transpose_k<<<dim3(32, 32, 8), dim3(32, 8)>>>(tp);
    }

    // 1) ONE launch: 7 GEMMs + attention + fused mp2/final gating
    {
        UberArgs ua;
        ua.A[0] = inputs;  ua.BT[0] = wt[0]; ua.bias[0] = b_emb;   ua.C[0] = p_dense;
        ua.A[1] = inputs;  ua.BT[1] = wt[1]; ua.bias[1] = nullptr; ua.C[1] = p_xf;
        ua.A[2] = inputs;  ua.BT[2] = wt[2]; ua.bias[2] = nullptr; ua.C[2] = p_xi;
        ua.A[3] = inputs;  ua.BT[3] = wt[3]; ua.bias[3] = nullptr; ua.C[3] = p_xo;
        ua.A[4] = h_state; ua.BT[4] = wt[4]; ua.bias[4] = b_uf;    ua.C[4] = p_gf;
        ua.A[5] = h_state; ua.BT[5] = wt[5]; ua.bias[5] = b_ui;    ua.C[5] = p_gi;
        ua.A[6] = h_state; ua.BT[6] = wt[6]; ua.bias[6] = b_uo;    ua.C[6] = p_go;
        ua.m_state = m_state;
        ua.mp  = p_mp;
        ua.BTg = wt[7];
        ua.bg  = b_g;
        ua.out = (float*)d_out;
        uber_kernel<<<N_UBER_BLK, 256, GEMM_SMEM>>>(ua);
    }
}